// round 9
// baseline (speedup 1.0000x reference)
#include <cuda_runtime.h>

// TriMipEncoding: x [N,3] in [0,1], fm [3,512,512,16] fp32. out [N,48].
//
// R9: 8 threads per (point,plane). t00/t01 (and t10/t11) are adjacent
// columns -> one contiguous 128B span per row. Each thread loads 16B from
// each of the two row spans (2 LDG.128 instead of 4), applies folded
// u/v weights, then shfl_xor(4)+add combines the texel pair. Gather
// line-visits drop 12 -> 9 per point. 2D block (24x8) removes the /3.
// Edge clamping via weight folding (exact clamp semantics).

#define PLANE 512

__device__ __forceinline__ float4 ldg_resident(const float4* p, unsigned long long pol) {
    float4 v;
    asm("ld.global.nc.L2::cache_hint.v4.f32 {%0,%1,%2,%3}, [%4], %5;"
        : "=f"(v.x), "=f"(v.y), "=f"(v.z), "=f"(v.w)
        : "l"(p), "l"(pol));
    return v;
}

__global__ void __launch_bounds__(192) trimip_kernel(
    const float* __restrict__ x,
    const float4* __restrict__ fm4,
    float4* __restrict__ out4,
    int n_pts)
{
    int tx = threadIdx.x;            // 0..23 : 3 planes x 8 lanes
    int p  = tx >> 3;                // plane 0..2
    int k  = tx & 7;                 // lane in 8-group
    int n  = blockIdx.x * 8 + threadIdx.y;
    bool valid = (n < n_pts);
    int nc = valid ? n : (n_pts - 1);    // clamp: keep full warp converged

    unsigned long long pol;
    asm("createpolicy.fractional.L2::evict_last.b64 %0, 1.0;" : "=l"(pol));

    float x0 = __ldg(x + nc * 3 + 0);
    float x1 = __ldg(x + nc * 3 + 1);
    float x2 = __ldg(x + nc * 3 + 2);

    // plane 0: (y,z) ; plane 1: (x,z) ; plane 2: (x,y)
    float cu = (p == 0) ? x1 : x0;
    float cv = (p == 2) ? x1 : x2;

    float u = cu * (float)PLANE - 0.5f;
    float v = cv * (float)PLANE - 0.5f;
    float i0f = floorf(u);
    float j0f = floorf(v);
    float fu = u - i0f;
    float fv = v - j0f;

    int i0 = (int)i0f;
    int i0c = min(max(i0,     0), PLANE - 1);
    int i1c = min(max(i0 + 1, 0), PLANE - 1);
    int j0c = min(max((int)j0f,     0), PLANE - 1);
    int j1c = min(max((int)j0f + 1, 0), PLANE - 1);

    // Span base column: span covers texels {ii, ii+1}; this lane owns texel it.
    int ii = min(max(i0, 0), PLANE - 2);
    int it = ii + (k >> 2);
    int c  = k & 3;

    // Folded u-weight for this lane's texel (exact clamp semantics at edges).
    float wu = (i0c == it ? (1.0f - fu) : 0.0f) + (i1c == it ? fu : 0.0f);
    float wv0 = wu * (1.0f - fv);
    float wv1 = wu * fv;

    // float4 index of texel (p, j, it) quad c: ((p*512 + j)*512 + it)*4 + c
    const float4* base = fm4 + ((size_t)p << 20) + (size_t)it * 4 + c;
    float4 s0 = ldg_resident(base + (size_t)j0c * (PLANE * 4), pol);
    float4 s1 = ldg_resident(base + (size_t)j1c * (PLANE * 4), pol);

    float4 part;
    part.x = wv0 * s0.x + wv1 * s1.x;
    part.y = wv0 * s0.y + wv1 * s1.y;
    part.z = wv0 * s0.z + wv1 * s1.z;
    part.w = wv0 * s0.w + wv1 * s1.w;

    // Combine texel-pair partials: lanes k and k+4 (xor 4 stays in 8-group,
    // groups are 8-aligned within the warp; all 32 lanes converged).
    float4 oth;
    oth.x = __shfl_xor_sync(0xffffffffu, part.x, 4);
    oth.y = __shfl_xor_sync(0xffffffffu, part.y, 4);
    oth.z = __shfl_xor_sync(0xffffffffu, part.z, 4);
    oth.w = __shfl_xor_sync(0xffffffffu, part.w, 4);

    if (valid && k < 4) {
        float4 r;
        r.x = part.x + oth.x;
        r.y = part.y + oth.y;
        r.z = part.z + oth.z;
        r.w = part.w + oth.w;
        __stcs(out4 + (size_t)n * 12 + p * 4 + c, r);
    }
}

extern "C" void kernel_launch(void* const* d_in, const int* in_sizes, int n_in,
                              void* d_out, int out_size)
{
    const float*  x   = (const float*)d_in[0];    // [N,3]
    const float4* fm4 = (const float4*)d_in[1];   // [3,512,512,16] as float4
    float4* out4 = (float4*)d_out;                // [N,48] as float4

    int n_pts = in_sizes[0] / 3;
    dim3 block(24, 8);                             // 192 threads = 8 points
    int blocks = (n_pts + 7) / 8;
    trimip_kernel<<<blocks, block>>>(x, fm4, out4, n_pts);
}

// round 10
// speedup vs baseline: 1.2670x; 1.2670x over previous
#include <cuda_runtime.h>

// TriMipEncoding: x [N,3] in [0,1], fm [3,512,512,16] fp32. out [N,48].
//
// R10 = R6 memory shape, but thread owns a QUAD-PAIR (32B, two adjacent
// float4 of one texel) -> 4x LDG.256 per unit instead of 8x LDG.128, one
// decode per pair instead of two. Wavefronts/line-visits unchanged (the
// memory floor), instruction count ~halved (ALU was 26.6%, issue 36.4%).
// 2 strided units per thread (R6's winning MLP structure), evict_last on
// fm via the direct .v8.b32 form, streaming stores.

#define PLANE_H 512
#define PLANE_W 512

struct F8 { float f[8]; };

__device__ __forceinline__ F8 ldg256_resident(const float* p) {
    F8 v;
    asm("ld.global.nc.L2::evict_last.v8.b32 {%0,%1,%2,%3,%4,%5,%6,%7}, [%8];"
        : "=f"(v.f[0]), "=f"(v.f[1]), "=f"(v.f[2]), "=f"(v.f[3]),
          "=f"(v.f[4]), "=f"(v.f[5]), "=f"(v.f[6]), "=f"(v.f[7])
        : "l"(p));
    return v;
}

struct Unit {
    const float* a00; const float* a01; const float* a10; const float* a11;
    float w00, w01, w10, w11;
};

__device__ __forceinline__ Unit decode(int idx, const float* __restrict__ x,
                                        const float* __restrict__ fm) {
    Unit un;
    int c2 = idx & 1;        // quad-pair: quads {0,1} or {2,3}
    int t  = idx >> 1;       // (point, plane)
    int n  = t / 3;          // magic-mul
    int p  = t - n * 3;

    float x0 = __ldg(x + n * 3 + 0);
    float x1 = __ldg(x + n * 3 + 1);
    float x2 = __ldg(x + n * 3 + 2);

    // plane 0: (y,z) ; plane 1: (x,z) ; plane 2: (x,y)
    float cu = (p == 0) ? x1 : x0;
    float cv = (p == 2) ? x1 : x2;

    float u = cu * (float)PLANE_W - 0.5f;
    float v = cv * (float)PLANE_H - 0.5f;
    float i0f = floorf(u);
    float j0f = floorf(v);
    float fu = u - i0f;
    float fv = v - j0f;

    int i0 = min(max((int)i0f,     0), PLANE_W - 1);
    int i1 = min(max((int)i0f + 1, 0), PLANE_W - 1);
    int j0 = min(max((int)j0f,     0), PLANE_H - 1);
    int j1 = min(max((int)j0f + 1, 0), PLANE_H - 1);

    un.w00 = (1.0f - fv) * (1.0f - fu);
    un.w01 = (1.0f - fv) * fu;
    un.w10 = fv * (1.0f - fu);
    un.w11 = fv * fu;

    // float offset of texel (p,j,i), quad-pair c2: ((p*H+j)*W + i)*16 + c2*8
    const float* base = fm + ((size_t)p * PLANE_H * PLANE_W * 16) + c2 * 8;
    size_t r0 = (size_t)j0 * (PLANE_W * 16);
    size_t r1 = (size_t)j1 * (PLANE_W * 16);
    un.a00 = base + r0 + (size_t)i0 * 16;
    un.a01 = base + r0 + (size_t)i1 * 16;
    un.a10 = base + r1 + (size_t)i0 * 16;
    un.a11 = base + r1 + (size_t)i1 * 16;
    return un;
}

__device__ __forceinline__ void blend_store(const Unit& un,
                                            const F8& a, const F8& b,
                                            const F8& d, const F8& e,
                                            float4* out4, int idx) {
    float4 r0, r1;
    r0.x = un.w00 * a.f[0] + un.w01 * b.f[0] + un.w10 * d.f[0] + un.w11 * e.f[0];
    r0.y = un.w00 * a.f[1] + un.w01 * b.f[1] + un.w10 * d.f[1] + un.w11 * e.f[1];
    r0.z = un.w00 * a.f[2] + un.w01 * b.f[2] + un.w10 * d.f[2] + un.w11 * e.f[2];
    r0.w = un.w00 * a.f[3] + un.w01 * b.f[3] + un.w10 * d.f[3] + un.w11 * e.f[3];
    r1.x = un.w00 * a.f[4] + un.w01 * b.f[4] + un.w10 * d.f[4] + un.w11 * e.f[4];
    r1.y = un.w00 * a.f[5] + un.w01 * b.f[5] + un.w10 * d.f[5] + un.w11 * e.f[5];
    r1.z = un.w00 * a.f[6] + un.w01 * b.f[6] + un.w10 * d.f[6] + un.w11 * e.f[6];
    r1.w = un.w00 * a.f[7] + un.w01 * b.f[7] + un.w10 * d.f[7] + un.w11 * e.f[7];
    // out float4 index = unit idx * 2 (+1): unit = (t, c2) -> n*12 + p*4 + c2*2
    __stcs(out4 + (size_t)idx * 2,     r0);
    __stcs(out4 + (size_t)idx * 2 + 1, r1);
}

__global__ void __launch_bounds__(128) trimip_kernel(
    const float* __restrict__ x,
    const float* __restrict__ fm,
    float4* __restrict__ out4,
    int half)   // = n_pts * 3 ; second unit at idx + half
{
    int idx = blockIdx.x * blockDim.x + threadIdx.x;
    if (idx >= half) return;

    Unit u0 = decode(idx,        x, fm);
    Unit u1 = decode(idx + half, x, fm);

    // Front-batch 8 x LDG.256 (same bytes-in-flight as R6's 8 x LDG.128 x2)
    F8 a0 = ldg256_resident(u0.a00);
    F8 b0 = ldg256_resident(u0.a01);
    F8 d0 = ldg256_resident(u0.a10);
    F8 e0 = ldg256_resident(u0.a11);
    F8 a1 = ldg256_resident(u1.a00);
    F8 b1 = ldg256_resident(u1.a01);
    F8 d1 = ldg256_resident(u1.a10);
    F8 e1 = ldg256_resident(u1.a11);

    blend_store(u0, a0, b0, d0, e0, out4, idx);
    blend_store(u1, a1, b1, d1, e1, out4, idx + half);
}

extern "C" void kernel_launch(void* const* d_in, const int* in_sizes, int n_in,
                              void* d_out, int out_size)
{
    const float* x  = (const float*)d_in[0];    // [N,3]
    const float* fm = (const float*)d_in[1];    // [3,512,512,16]
    float4* out4 = (float4*)d_out;              // [N,48] as float4

    int n_pts = in_sizes[0] / 3;
    int half = n_pts * 3;                        // n_pts*6 pair-units / 2
    int threads = 128;
    int blocks = (half + threads - 1) / threads;
    trimip_kernel<<<blocks, threads>>>(x, fm, out4, half);
}